// round 8
// baseline (speedup 1.0000x reference)
#include <cuda_runtime.h>
#include <cstdint>

typedef unsigned long long ull;
#define FULLMASK 0xffffffffu

constexpr int MAX_ITER = 8192;
constexpr int NNODES   = MAX_ITER + 1;   // 8193
constexpr int NBLK     = 256;            // 32 iterations per block
constexpr int NTHREADS = 1024;           // 32 warps
constexpr int CSIZE    = 8;
constexpr int SERIAL_WARP = 31;

constexpr int NODES_PAD = 8208;          // 8193 + sentinel pad
constexpr int NSLOT_PAD = 34;            // 0..30 samples, 31/32 = sample-31 halves

// per-CTA smem layout:
//   nodes float2[8208] | samps float2[8192] | bests ull[4][8][34]
//   P ull[2][32] | cand float2[32]
//   mbars ull[8]: [0,1]=nodes ring, [2,3]=P ring, [4..7]=bests objs
constexpr size_t OFF_SAMPS = (size_t)NODES_PAD * sizeof(float2);
constexpr size_t OFF_BESTS = OFF_SAMPS + (size_t)MAX_ITER * sizeof(float2);
constexpr size_t OFF_P     = OFF_BESTS + 4ull * CSIZE * NSLOT_PAD * sizeof(ull);
constexpr size_t OFF_CAND  = OFF_P + 2ull * 32 * sizeof(ull);
constexpr size_t OFF_MBARS = OFF_CAND + 32ull * sizeof(float2);
constexpr size_t SMEM_BYTES = OFF_MBARS + 8ull * sizeof(ull);

constexpr ull KEY_INF = ((ull)0x7f800000u << 32);

__device__ __forceinline__ uint32_t smem_u32(const void* p) {
    return (uint32_t)__cvta_generic_to_shared(p);
}
__device__ __forceinline__ uint32_t my_ctarank() {
    uint32_t r; asm("mov.u32 %0, %%cluster_ctarank;" : "=r"(r)); return r;
}
__device__ __forceinline__ uint32_t mapa_u32(uint32_t laddr, uint32_t rank) {
    uint32_t r; asm("mapa.shared::cluster.u32 %0, %1, %2;" : "=r"(r) : "r"(laddr), "r"(rank));
    return r;
}
__device__ __forceinline__ void st_cluster_u64(uint32_t raddr, ull v) {
    asm volatile("st.shared::cluster.u64 [%0], %1;" :: "r"(raddr), "l"(v) : "memory");
}
__device__ __forceinline__ void mbar_init(uint32_t a, uint32_t cnt) {
    asm volatile("mbarrier.init.shared.b64 [%0], %1;" :: "r"(a), "r"(cnt) : "memory");
}
__device__ __forceinline__ void mbar_arrive_cta(uint32_t a) {
    asm volatile("mbarrier.arrive.release.cta.shared::cta.b64 _, [%0];" :: "r"(a) : "memory");
}
__device__ __forceinline__ void mbar_arrive_cluster_remote(uint32_t raddr) {
    asm volatile("mbarrier.arrive.release.cluster.shared::cluster.b64 _, [%0];"
                 :: "r"(raddr) : "memory");
}
__device__ __forceinline__ void mbar_wait_cta(uint32_t a, uint32_t phase) {
    asm volatile(
        "{\n\t.reg .pred P;\n\t"
        "WL_%=:\n\t"
        "mbarrier.try_wait.parity.acquire.cta.shared::cta.b64 P, [%0], %1, 0x989680;\n\t"
        "@P bra.uni WD_%=;\n\t"
        "bra.uni WL_%=;\n\t"
        "WD_%=:\n\t}"
        :: "r"(a), "r"(phase) : "memory");
}
__device__ __forceinline__ void mbar_wait_cluster(uint32_t a, uint32_t phase) {
    asm volatile(
        "{\n\t.reg .pred P;\n\t"
        "WL_%=:\n\t"
        "mbarrier.try_wait.parity.acquire.cluster.shared::cta.b64 P, [%0], %1, 0x989680;\n\t"
        "@P bra.uni WD_%=;\n\t"
        "bra.uni WL_%=;\n\t"
        "WD_%=:\n\t}"
        :: "r"(a), "r"(phase) : "memory");
}
#define CLUSTER_ARRIVE() asm volatile("barrier.cluster.arrive.aligned;" ::: "memory")
#define CLUSTER_WAIT()   asm volatile("barrier.cluster.wait.aligned;"   ::: "memory")

__device__ __forceinline__ ull bfly_min(ull key) {
    #pragma unroll
    for (int o = 16; o > 0; o >>= 1) {
        ull other = __shfl_xor_sync(FULLMASK, key, o);
        key = (other < key) ? other : key;
    }
    return key;
}

__device__ __forceinline__ void steer(float fx, float fy, float sx, float sy, float d2,
                                      float& ox, float& oy) {
    float dist = __fsqrt_rn(__fadd_rn(d2, 1e-12f));
    float q    = __fdiv_rn(5.0f, dist);
    float sc   = (dist > 5.0f) ? q : 1.0f;
    ox = __fadd_rn(fx, __fmul_rn(__fadd_rn(sx, -fx), sc));
    oy = __fadd_rn(fy, __fmul_rn(__fadd_rn(sy, -fy), sc));
}

__device__ __forceinline__ float d2_rn(float nx, float ny, float sx, float sy) {
    float dx = __fadd_rn(nx, -sx), dy = __fadd_rn(ny, -sy);
    return __fadd_rn(__fmul_rn(dx, dx), __fmul_rn(dy, dy));
}

// per-lane scan partial, 128-node tiles t = t0, t0+tstep, ... while 128t <= bound.
// sentinels (+inf) make over-reads harmless; races with serial STS.64 are
// tear-free and value-correct (either sentinel or final node).
__device__ __forceinline__ ull scan_part(const float2* __restrict__ nodes_s, float2 s,
                                         int bound, int t0, int tstep, int lane) {
    const float INF = __int_as_float(0x7f800000);
    float bd2 = INF; int bidx = 0;
    for (int t = t0; 128 * t <= bound; t += tstep) {
        int i0 = 128 * t + 2 * lane;
        float4 a = *reinterpret_cast<const float4*>(&nodes_s[i0]);
        float4 c = *reinterpret_cast<const float4*>(&nodes_s[i0 + 64]);
        float da0 = d2_rn(a.x, a.y, s.x, s.y);
        float da1 = d2_rn(a.z, a.w, s.x, s.y);
        float dc0 = d2_rn(c.x, c.y, s.x, s.y);
        float dc1 = d2_rn(c.z, c.w, s.x, s.y);
        float ma = fminf(da0, da1); int ia = (da0 <= da1) ? i0 : i0 + 1;
        float mc = fminf(dc0, dc1); int ic = (dc0 <= dc1) ? i0 + 64 : i0 + 65;
        float m  = fminf(ma, mc);   int mi = (ma <= mc) ? ia : ic;   // lower idx on tie
        if (m < bd2) { bd2 = m; bidx = mi; }                         // strict <
    }
    return ((ull)__float_as_uint(bd2) << 32) | (uint32_t)bidx;
}

__global__ void __launch_bounds__(NTHREADS, 1) __cluster_dims__(CSIZE, 1, 1)
rrt_kernel(const float* __restrict__ state,
           const float* __restrict__ goal,
           const float* __restrict__ u,
           const float* __restrict__ r,
           float* __restrict__ out)
{
    extern __shared__ char smem_raw[];
    float2* nodes_s = (float2*)smem_raw;
    float2* samps   = (float2*)(smem_raw + OFF_SAMPS);
    ull (*bests)[CSIZE][NSLOT_PAD] = (ull (*)[CSIZE][NSLOT_PAD])(smem_raw + OFF_BESTS);
    ull (*P)[32]    = (ull (*)[32])(smem_raw + OFF_P);
    float2* cand    = (float2*)(smem_raw + OFF_CAND);
    ull* mbars      = (ull*)(smem_raw + OFF_MBARS);

    const int tid  = threadIdx.x;
    const int lane = tid & 31;
    const int warp = tid >> 5;
    const uint32_t crank = my_ctarank();
    const float INF = __int_as_float(0x7f800000);

    const uint32_t mb_nodes0 = smem_u32(&mbars[0]);   // ring objs at +8*idx
    const uint32_t mb_P0     = smem_u32(&mbars[2]);   // ring objs at +8*idx
    const uint32_t mb_bests0 = smem_u32(&mbars[4]);   // objs 0..3 at +8*obj

    // ---- init ----
    for (int i = tid; i < NODES_PAD; i += NTHREADS)
        nodes_s[i] = make_float2(INF, INF);
    const float gx = goal[0], gy = goal[1];
    for (int i = tid; i < MAX_ITER; i += NTHREADS) {
        float ui = u[i];
        float sx = __fmul_rn(r[2 * i],     200.0f);
        float sy = __fmul_rn(r[2 * i + 1], 200.0f);
        if (ui < 0.1f) { sx = gx; sy = gy; }
        samps[i] = make_float2(sx, sy);
    }
    if (tid < 32) cand[tid] = make_float2(INF, INF);   // block "-1" candidates
    if (tid == 0) {
        float2 st0 = make_float2(state[0], state[1]);
        nodes_s[0] = st0;
        cand[31]   = st0;                              // idx 0 for block-0 delta32
        mbar_init(mb_nodes0 + 0, 32);                  // serial warp lanes
        mbar_init(mb_nodes0 + 8, 32);
        mbar_init(mb_P0 + 0, 31);                      // scan warps' lane-0
        mbar_init(mb_P0 + 8, 31);
        for (int o = 0; o < 4; o++)
            mbar_init(mb_bests0 + 8 * o, 33 * CSIZE);
    }
    __syncthreads();
    CLUSTER_ARRIVE();
    CLUSTER_WAIT();

    for (int b = 0; b < NBLK; b++) {
        if (warp == SERIAL_WARP) {
            // ===== serial warp: fully self-sufficient block b =====
            const float2 s2 = samps[32 * b + lane];
            const float sx = s2.x, sy = s2.y;
            float bd2 = INF; int bidx = 0;
            const float4* cand4 = (const float4*)cand;
            #pragma unroll
            for (int l = 0; l < 32; l += 2) {
                float4 c = cand4[l >> 1];
                float d0 = d2_rn(c.x, c.y, sx, sy);
                float d1 = d2_rn(c.z, c.w, sx, sy);
                if (d0 < bd2) { bd2 = d0; bidx = 32 * b - 31 + l; }
                if (d1 < bd2) { bd2 = d1; bidx = 32 * b - 31 + l + 1; }
            }
            // merge P(b) (produced at iteration j=b-1 -> P-ring obj (b-1)&1)
            if (b > 0) {
                mbar_wait_cta(mb_P0 + 8 * ((b - 1) & 1), ((b - 1) >> 1) & 1);
                ull p = P[b & 1][lane];
                float pd2 = __uint_as_float((uint32_t)(p >> 32));
                if (pd2 <= bd2) { bd2 = pd2; bidx = (int)(uint32_t)p; }  // P idx smaller
            }
            float2 f = nodes_s[bidx];
            float cx, cy;
            steer(f.x, f.y, sx, sy, bd2, cx, cy);

            // speculative fixup (lane j owns sample 32b+j)
            while (true) {
                cand[lane] = make_float2(cx, cy);
                __syncwarp();
                float vmin = INF; int vl = 0;
                #pragma unroll
                for (int l = 0; l < 32; l += 2) {
                    float4 c = cand4[l >> 1];
                    float e0 = d2_rn(c.x, c.y, sx, sy);
                    float e1 = d2_rn(c.z, c.w, sx, sy);
                    if (l     < lane && e0 < vmin) { vmin = e0; vl = l; }
                    if (l + 1 < lane && e1 < vmin) { vmin = e1; vl = l + 1; }
                }
                unsigned mask = __ballot_sync(FULLMASK, vmin < bd2);   // strict <
                if (!mask) break;
                int F2 = __ffs((int)mask) - 1;       // first violator vs finals only
                if (lane == F2) {
                    bd2 = vmin;
                    float2 c = cand[vl];
                    steer(c.x, c.y, sx, sy, bd2, cx, cy);
                }
            }
            nodes_s[32 * b + 1 + lane] = make_float2(cx, cy);
            if (b < NBLK - 1)
                mbar_arrive_cta(mb_nodes0 + 8 * (b & 1));   // all 32 lanes
        } else {
            // ===== scan warps (0..30): iteration j = b, off critical path =====
            const int j = b;
            if (j >= NBLK - 1) continue;
            if (j >= 1) {
                // nodes of block j-1 -> nodes-ring obj (j-1)&1
                mbar_wait_cta(mb_nodes0 + 8 * ((j - 1) & 1), ((j - 1) >> 1) & 1);
                mbar_wait_cluster(mb_bests0 + 8 * ((j - 1) & 3), ((j - 1) >> 2) & 1);
            }
            const int obj_r = (j - 1) & 3;
            int nidx = 32 * j - 31 + lane;                 // block j-1 output node
            float2 n = nodes_s[nidx >= 0 ? nidx : 0];

            // ---- produce P(j+1), slot = warp ----
            {
                const float2 s = samps[32 * (j + 1) + warp];
                ull key = KEY_INF;
                if (j >= 1 && lane < CSIZE) key = bests[obj_r][lane][warp];
                if (nidx >= 0) {
                    float d2 = d2_rn(n.x, n.y, s.x, s.y);
                    ull ck = ((ull)__float_as_uint(d2) << 32) | (uint32_t)nidx;
                    key = (ck < key) ? ck : key;
                }
                key = bfly_min(key);
                if (lane == 0) P[(j + 1) & 1][warp] = key;
            }
            if (warp == 30) {                              // P(j+1) slot 31
                const float2 s = samps[32 * (j + 1) + 31];
                ull key = KEY_INF;
                if (j >= 1) {
                    if (lane < CSIZE)            key = bests[obj_r][lane][31];
                    else if (lane < 2 * CSIZE)   key = bests[obj_r][lane - CSIZE][32];
                }
                if (nidx >= 0) {
                    float d2 = d2_rn(n.x, n.y, s.x, s.y);
                    ull ck = ((ull)__float_as_uint(d2) << 32) | (uint32_t)nidx;
                    key = (ck < key) ? ck : key;
                }
                key = bfly_min(key);
                if (lane == 0) P[(j + 1) & 1][31] = key;
            }
            if (lane == 0) mbar_arrive_cta(mb_P0 + 8 * (j & 1));  // production j

            // ---- scan + cross-CTA send for bests(j+2) (slack-filled) ----
            if (j <= NBLK - 3) {
                const int obj = j & 3;
                ull pk = scan_part(nodes_s, samps[32 * (j + 2) + warp],
                                   32 * j, (int)crank, CSIZE, lane);
                pk = bfly_min(pk);
                if (lane < CSIZE) {
                    uint32_t la = smem_u32(&bests[obj][crank][warp]);
                    st_cluster_u64(mapa_u32(la, (uint32_t)lane), pk);
                    mbar_arrive_cluster_remote(mapa_u32(mb_bests0 + 8 * obj, (uint32_t)lane));
                }
                if (warp == 29 || warp == 30) {            // sample-31 scan split
                    int t0 = (warp == 29) ? (int)crank : (int)crank + CSIZE;
                    ull pk2 = scan_part(nodes_s, samps[32 * (j + 2) + 31],
                                        32 * j, t0, 2 * CSIZE, lane);
                    pk2 = bfly_min(pk2);
                    int slot = (warp == 29) ? 31 : 32;
                    if (lane < CSIZE) {
                        uint32_t la = smem_u32(&bests[obj][crank][slot]);
                        st_cluster_u64(mapa_u32(la, (uint32_t)lane), pk2);
                        mbar_arrive_cluster_remote(mapa_u32(mb_bests0 + 8 * obj, (uint32_t)lane));
                    }
                }
            }
        }
    }

    __syncthreads();
    CLUSTER_ARRIVE();
    CLUSTER_WAIT();

    if (crank == 0) {
        const float* ns = reinterpret_cast<const float*>(nodes_s);
        for (int i = tid; i < 2 * NNODES; i += NTHREADS)
            out[i] = ns[i];
    }
}

extern "C" void kernel_launch(void* const* d_in, const int* in_sizes, int n_in,
                              void* d_out, int out_size)
{
    const float* state = (const float*)d_in[0];
    const float* goal  = (const float*)d_in[1];
    const float* u     = (const float*)d_in[2];
    const float* r     = (const float*)d_in[3];
    float* out = (float*)d_out;

    cudaFuncSetAttribute(rrt_kernel,
                         cudaFuncAttributeMaxDynamicSharedMemorySize,
                         (int)SMEM_BYTES);
    rrt_kernel<<<CSIZE, NTHREADS, SMEM_BYTES>>>(state, goal, u, r, out);
}

// round 9
// speedup vs baseline: 1.4597x; 1.4597x over previous
#include <cuda_runtime.h>
#include <cstdint>

typedef unsigned long long ull;
#define FULLMASK 0xffffffffu

constexpr int MAX_ITER = 8192;
constexpr int NNODES   = MAX_ITER + 1;   // 8193
constexpr int NBLK     = 256;            // 32 iterations per block
constexpr int NTHREADS = 1024;           // 32 warps
constexpr int CSIZE    = 8;
constexpr int SERIAL_WARP = 31;

constexpr int NODES_PAD = 8208;          // 8193 + sentinel pad (scan reads < 8208)
constexpr int NSLOT_PAD = 34;            // 0..30 samples, 31/32 = sample-31 halves

// per-CTA smem layout:
//   nodes float2[8208] | samps float2[8192] | bests ull[4][8][34]
//   cand float2[2][32] (ring of block candidates)
//   mbars ull[8]: [0..3]=nodes ring objs, [4..7]=bests objs
constexpr size_t OFF_SAMPS = (size_t)NODES_PAD * sizeof(float2);
constexpr size_t OFF_BESTS = OFF_SAMPS + (size_t)MAX_ITER * sizeof(float2);
constexpr size_t OFF_CAND  = OFF_BESTS + 4ull * CSIZE * NSLOT_PAD * sizeof(ull);
constexpr size_t OFF_MBARS = OFF_CAND + 64ull * sizeof(float2);
constexpr size_t SMEM_BYTES = OFF_MBARS + 8ull * sizeof(ull);

constexpr ull KEY_INF = ((ull)0x7f800000u << 32);

__device__ __forceinline__ uint32_t smem_u32(const void* p) {
    return (uint32_t)__cvta_generic_to_shared(p);
}
__device__ __forceinline__ uint32_t my_ctarank() {
    uint32_t r; asm("mov.u32 %0, %%cluster_ctarank;" : "=r"(r)); return r;
}
__device__ __forceinline__ uint32_t mapa_u32(uint32_t laddr, uint32_t rank) {
    uint32_t r; asm("mapa.shared::cluster.u32 %0, %1, %2;" : "=r"(r) : "r"(laddr), "r"(rank));
    return r;
}
__device__ __forceinline__ void st_cluster_u64(uint32_t raddr, ull v) {
    asm volatile("st.shared::cluster.u64 [%0], %1;" :: "r"(raddr), "l"(v) : "memory");
}
__device__ __forceinline__ void mbar_init(uint32_t a, uint32_t cnt) {
    asm volatile("mbarrier.init.shared.b64 [%0], %1;" :: "r"(a), "r"(cnt) : "memory");
}
__device__ __forceinline__ void mbar_arrive_cta(uint32_t a) {
    asm volatile("mbarrier.arrive.release.cta.shared::cta.b64 _, [%0];" :: "r"(a) : "memory");
}
__device__ __forceinline__ void mbar_arrive_cluster_remote(uint32_t raddr) {
    asm volatile("mbarrier.arrive.release.cluster.shared::cluster.b64 _, [%0];"
                 :: "r"(raddr) : "memory");
}
__device__ __forceinline__ void mbar_wait_cta(uint32_t a, uint32_t phase) {
    asm volatile(
        "{\n\t.reg .pred P;\n\t"
        "WL_%=:\n\t"
        "mbarrier.try_wait.parity.acquire.cta.shared::cta.b64 P, [%0], %1, 0x989680;\n\t"
        "@P bra.uni WD_%=;\n\t"
        "bra.uni WL_%=;\n\t"
        "WD_%=:\n\t}"
        :: "r"(a), "r"(phase) : "memory");
}
__device__ __forceinline__ void mbar_wait_cluster(uint32_t a, uint32_t phase) {
    asm volatile(
        "{\n\t.reg .pred P;\n\t"
        "WL_%=:\n\t"
        "mbarrier.try_wait.parity.acquire.cluster.shared::cta.b64 P, [%0], %1, 0x989680;\n\t"
        "@P bra.uni WD_%=;\n\t"
        "bra.uni WL_%=;\n\t"
        "WD_%=:\n\t}"
        :: "r"(a), "r"(phase) : "memory");
}
#define CLUSTER_ARRIVE() asm volatile("barrier.cluster.arrive.aligned;" ::: "memory")
#define CLUSTER_WAIT()   asm volatile("barrier.cluster.wait.aligned;"   ::: "memory")

__device__ __forceinline__ ull bfly_min(ull key) {
    #pragma unroll
    for (int o = 16; o > 0; o >>= 1) {
        ull other = __shfl_xor_sync(FULLMASK, key, o);
        key = (other < key) ? other : key;
    }
    return key;
}

__device__ __forceinline__ void steer(float fx, float fy, float sx, float sy, float d2,
                                      float& ox, float& oy) {
    float dist = __fsqrt_rn(__fadd_rn(d2, 1e-12f));
    float q    = __fdiv_rn(5.0f, dist);
    float sc   = (dist > 5.0f) ? q : 1.0f;
    ox = __fadd_rn(fx, __fmul_rn(__fadd_rn(sx, -fx), sc));
    oy = __fadd_rn(fy, __fmul_rn(__fadd_rn(sy, -fy), sc));
}

__device__ __forceinline__ float d2_rn(float nx, float ny, float sx, float sy) {
    float dx = __fadd_rn(nx, -sx), dy = __fadd_rn(ny, -sy);
    return __fadd_rn(__fmul_rn(dx, dx), __fmul_rn(dy, dy));
}

// per-lane scan partial, 128-node tiles t = t0, t0+tstep, ... while 128t <= bound.
// sentinels (+inf) make over-reads harmless; races with serial STS.64 are
// tear-free; any raced entry is a TRUE (d2,idx) pair, so u64-min stays exact.
__device__ __forceinline__ ull scan_part(const float2* __restrict__ nodes_s, float2 s,
                                         int bound, int t0, int tstep, int lane) {
    const float INF = __int_as_float(0x7f800000);
    float bd2 = INF; int bidx = 0;
    for (int t = t0; 128 * t <= bound; t += tstep) {
        int i0 = 128 * t + 2 * lane;
        float4 a = *reinterpret_cast<const float4*>(&nodes_s[i0]);
        float4 c = *reinterpret_cast<const float4*>(&nodes_s[i0 + 64]);
        float da0 = d2_rn(a.x, a.y, s.x, s.y);
        float da1 = d2_rn(a.z, a.w, s.x, s.y);
        float dc0 = d2_rn(c.x, c.y, s.x, s.y);
        float dc1 = d2_rn(c.z, c.w, s.x, s.y);
        float ma = fminf(da0, da1); int ia = (da0 <= da1) ? i0 : i0 + 1;
        float mc = fminf(dc0, dc1); int ic = (dc0 <= dc1) ? i0 + 64 : i0 + 65;
        float m  = fminf(ma, mc);   int mi = (ma <= mc) ? ia : ic;   // lower idx on tie
        if (m < bd2) { bd2 = m; bidx = mi; }                         // strict <
    }
    return ((ull)__float_as_uint(bd2) << 32) | (uint32_t)bidx;
}

__global__ void __launch_bounds__(NTHREADS, 1) __cluster_dims__(CSIZE, 1, 1)
rrt_kernel(const float* __restrict__ state,
           const float* __restrict__ goal,
           const float* __restrict__ u,
           const float* __restrict__ r,
           float* __restrict__ out)
{
    extern __shared__ char smem_raw[];
    float2* nodes_s = (float2*)smem_raw;
    float2* samps   = (float2*)(smem_raw + OFF_SAMPS);
    ull (*bests)[CSIZE][NSLOT_PAD] = (ull (*)[CSIZE][NSLOT_PAD])(smem_raw + OFF_BESTS);
    float2* cand    = (float2*)(smem_raw + OFF_CAND);   // [2][32] ring
    ull* mbars      = (ull*)(smem_raw + OFF_MBARS);

    const int tid  = threadIdx.x;
    const int lane = tid & 31;
    const int warp = tid >> 5;
    const uint32_t crank = my_ctarank();
    const float INF = __int_as_float(0x7f800000);

    const uint32_t mb_nodes0 = smem_u32(&mbars[0]);   // 4 ring objs at +8*idx
    const uint32_t mb_bests0 = smem_u32(&mbars[4]);   // 4 objs at +8*idx

    // ---- init ----
    for (int i = tid; i < NODES_PAD; i += NTHREADS)
        nodes_s[i] = make_float2(INF, INF);
    const float gx = goal[0], gy = goal[1];
    for (int i = tid; i < MAX_ITER; i += NTHREADS) {
        float ui = u[i];
        float sx = __fmul_rn(r[2 * i],     200.0f);
        float sy = __fmul_rn(r[2 * i + 1], 200.0f);
        if (ui < 0.1f) { sx = gx; sy = gy; }
        samps[i] = make_float2(sx, sy);
    }
    if (tid < 64) cand[tid] = make_float2(INF, INF);   // blocks "-2","-1"
    if (tid == 0) {
        float2 st0 = make_float2(state[0], state[1]);
        nodes_s[0] = st0;
        // block "-1" ring half = parity 1; slot 31 <-> idx 32*0-31+31 = 0 = root
        cand[32 + 31] = st0;
        for (int o = 0; o < 4; o++) {
            mbar_init(mb_nodes0 + 8 * o, 32);          // serial warp lanes
            mbar_init(mb_bests0 + 8 * o, 33 * CSIZE);  // 33 slots x 8 src CTAs
        }
    }
    __syncthreads();
    CLUSTER_ARRIVE();
    CLUSTER_WAIT();

    for (int b = 0; b < NBLK; b++) {
        if (warp == SERIAL_WARP) {
            // ===== serial warp: fully self-sufficient block b =====
            const float2 s2 = samps[32 * b + lane];
            const float sx = s2.x, sy = s2.y;

            // delta64 over cand ring: older half (block b-2, parity b&1, base 32b-63)
            // then newer half (block b-1, base 32b-31); increasing idx + strict <
            float bd2 = INF; int bidx = 0;
            {
                const float4* oldh = (const float4*)(cand + 32 * (b & 1));
                const float4* newh = (const float4*)(cand + 32 * ((b - 1) & 1));
                #pragma unroll
                for (int l = 0; l < 32; l += 2) {
                    float4 c = oldh[l >> 1];
                    float d0 = d2_rn(c.x, c.y, sx, sy);
                    float d1 = d2_rn(c.z, c.w, sx, sy);
                    if (d0 < bd2) { bd2 = d0; bidx = 32 * b - 63 + l; }
                    if (d1 < bd2) { bd2 = d1; bidx = 32 * b - 63 + l + 1; }
                }
                #pragma unroll
                for (int l = 0; l < 32; l += 2) {
                    float4 c = newh[l >> 1];
                    float d0 = d2_rn(c.x, c.y, sx, sy);
                    float d1 = d2_rn(c.z, c.w, sx, sy);
                    if (d0 < bd2) { bd2 = d0; bidx = 32 * b - 31 + l; }
                    if (d1 < bd2) { bd2 = d1; bidx = 32 * b - 31 + l + 1; }
                }
            }
            // merge bests(b): covers [0, 32b-64], sent at iteration b-2 (2 blocks slack)
            if (b >= 2) {
                const int obj = (b - 2) & 3;
                mbar_wait_cluster(mb_bests0 + 8 * obj, ((b - 2) >> 2) & 1);
                ull kk = KEY_INF;
                #pragma unroll
                for (int c = 0; c < CSIZE; c++) {
                    ull k2 = bests[obj][c][lane];
                    kk = (k2 < kk) ? k2 : kk;
                }
                if (lane == 31) {
                    #pragma unroll
                    for (int c = 0; c < CSIZE; c++) {
                        ull k2 = bests[obj][c][32];
                        kk = (k2 < kk) ? k2 : kk;
                    }
                }
                ull dk = ((ull)__float_as_uint(bd2) << 32) | (uint32_t)bidx;
                if (kk < dk) {                       // u64: exact (d2, idx) order
                    bd2  = __uint_as_float((uint32_t)(kk >> 32));
                    bidx = (int)(uint32_t)kk;
                }
            }
            float2 f = nodes_s[bidx];
            float cx, cy;
            steer(f.x, f.y, sx, sy, bd2, cx, cy);

            // speculative fixup; working buffer = ring half b&1 (old data consumed)
            float2* wcand = cand + 32 * (b & 1);
            const float4* wcand4 = (const float4*)wcand;
            __syncwarp();                            // delta reads done before overwrite
            while (true) {
                wcand[lane] = make_float2(cx, cy);
                __syncwarp();
                float vmin = INF; int vl = 0;
                #pragma unroll
                for (int l = 0; l < 32; l += 2) {
                    float4 c = wcand4[l >> 1];
                    float e0 = d2_rn(c.x, c.y, sx, sy);
                    float e1 = d2_rn(c.z, c.w, sx, sy);
                    if (l     < lane && e0 < vmin) { vmin = e0; vl = l; }
                    if (l + 1 < lane && e1 < vmin) { vmin = e1; vl = l + 1; }
                }
                unsigned mask = __ballot_sync(FULLMASK, vmin < bd2);   // strict <
                if (!mask) break;
                int F2 = __ffs((int)mask) - 1;       // first violator vs finals only
                if (lane == F2) {
                    bd2 = vmin;
                    float2 c = wcand[vl];
                    steer(c.x, c.y, sx, sy, bd2, cx, cy);
                }
            }
            __syncwarp();
            nodes_s[32 * b + 1 + lane] = make_float2(cx, cy);
            if (b < NBLK - 1)
                mbar_arrive_cta(mb_nodes0 + 8 * (b & 3));   // all 32 lanes
        } else {
            // ===== scan warps (0..30): iteration j = b, entirely off-path =====
            const int j = b;
            if (j > NBLK - 3) continue;               // no consumer remains
            if (j >= 1)                               // nodes [0,32j] final
                mbar_wait_cta(mb_nodes0 + 8 * ((j - 1) & 3), ((j - 1) >> 2) & 1);

            const int obj = j & 3;                    // consumed by serial block j+2
            ull pk = scan_part(nodes_s, samps[32 * (j + 2) + warp],
                               32 * j, (int)crank, CSIZE, lane);
            pk = bfly_min(pk);
            if (lane < CSIZE) {
                uint32_t la = smem_u32(&bests[obj][crank][warp]);
                st_cluster_u64(mapa_u32(la, (uint32_t)lane), pk);
                mbar_arrive_cluster_remote(mapa_u32(mb_bests0 + 8 * obj, (uint32_t)lane));
            }
            if (warp == 29 || warp == 30) {           // sample-31 scan split halves
                int t0 = (warp == 29) ? (int)crank : (int)crank + CSIZE;
                ull pk2 = scan_part(nodes_s, samps[32 * (j + 2) + 31],
                                    32 * j, t0, 2 * CSIZE, lane);
                pk2 = bfly_min(pk2);
                int slot = (warp == 29) ? 31 : 32;
                if (lane < CSIZE) {
                    uint32_t la = smem_u32(&bests[obj][crank][slot]);
                    st_cluster_u64(mapa_u32(la, (uint32_t)lane), pk2);
                    mbar_arrive_cluster_remote(mapa_u32(mb_bests0 + 8 * obj, (uint32_t)lane));
                }
            }
        }
    }

    __syncthreads();
    CLUSTER_ARRIVE();
    CLUSTER_WAIT();

    if (crank == 0) {
        const float* ns = reinterpret_cast<const float*>(nodes_s);
        for (int i = tid; i < 2 * NNODES; i += NTHREADS)
            out[i] = ns[i];
    }
}

extern "C" void kernel_launch(void* const* d_in, const int* in_sizes, int n_in,
                              void* d_out, int out_size)
{
    const float* state = (const float*)d_in[0];
    const float* goal  = (const float*)d_in[1];
    const float* u     = (const float*)d_in[2];
    const float* r     = (const float*)d_in[3];
    float* out = (float*)d_out;

    cudaFuncSetAttribute(rrt_kernel,
                         cudaFuncAttributeMaxDynamicSharedMemorySize,
                         (int)SMEM_BYTES);
    rrt_kernel<<<CSIZE, NTHREADS, SMEM_BYTES>>>(state, goal, u, r, out);
}